// round 8
// baseline (speedup 1.0000x reference)
#include <cuda_runtime.h>
#include <cstdint>

#define B_BAGS 16384

// Per-table exclusive prefix offsets (scratch, computed each launch).
__device__ int g_off[4][B_BAGS + 1];

// ---------------------------------------------------------------------------
// Scan kernel: one block per table, 1024 threads, 16 lens each, shfl-scan.
// ---------------------------------------------------------------------------
__global__ void scan_kernel(const int* __restrict__ l0, const int* __restrict__ l1,
                            const int* __restrict__ l2, const int* __restrict__ l3) {
    const int* lens = (blockIdx.x == 0) ? l0 : (blockIdx.x == 1) ? l1
                    : (blockIdx.x == 2) ? l2 : l3;
    int* off = g_off[blockIdx.x];
    __shared__ int warp_sums[32];

    int t    = threadIdx.x;
    int wid  = t >> 5;
    int lane = t & 31;

    int4 v0 = ((const int4*)lens)[t * 4 + 0];
    int4 v1 = ((const int4*)lens)[t * 4 + 1];
    int4 v2 = ((const int4*)lens)[t * 4 + 2];
    int4 v3 = ((const int4*)lens)[t * 4 + 3];
    int vals[16] = {v0.x, v0.y, v0.z, v0.w, v1.x, v1.y, v1.z, v1.w,
                    v2.x, v2.y, v2.z, v2.w, v3.x, v3.y, v3.z, v3.w};

    int s = 0;
    int pre[16];
#pragma unroll
    for (int k = 0; k < 16; k++) { pre[k] = s; s += vals[k]; }

    int incl = s;
#pragma unroll
    for (int d = 1; d < 32; d <<= 1) {
        int x = __shfl_up_sync(0xffffffffu, incl, d);
        if (lane >= d) incl += x;
    }
    if (lane == 31) warp_sums[wid] = incl;
    __syncthreads();

    if (wid == 0) {
        int w = warp_sums[lane];
        int wincl = w;
#pragma unroll
        for (int d = 1; d < 32; d <<= 1) {
            int x = __shfl_up_sync(0xffffffffu, wincl, d);
            if (lane >= d) wincl += x;
        }
        warp_sums[lane] = wincl - w;
    }
    __syncthreads();

    int base = warp_sums[wid] + (incl - s);
#pragma unroll
    for (int k = 0; k < 16; k++) off[t * 16 + k] = base + pre[k];
    if (t == 1023) off[B_BAGS] = base + s;
}

// ---------------------------------------------------------------------------
// Pooling kernel: warp per (bag, table), 8 warps/block, table-major grid.
// __launch_bounds__(256, 2): cap occupancy at 2 blocks/SM worth of regs
// (128/thread) so ptxas can hold 8-16 gather loads in flight per warp.
// ---------------------------------------------------------------------------
__global__ __launch_bounds__(256, 2)
void pool_kernel(const float* __restrict__ W0, const float* __restrict__ W1,
                 const float* __restrict__ W2, const float* __restrict__ W3,
                 const int* __restrict__ ids0, const int* __restrict__ ids1,
                 const int* __restrict__ ids2, const int* __restrict__ ids3,
                 float* __restrict__ out) {
    int table = blockIdx.x >> 11;              // 2048 blocks per table
    int bag   = ((blockIdx.x & 2047) << 3) + (threadIdx.x >> 5);
    int lane  = threadIdx.x & 31;

    const int* off = g_off[table];
    int s = off[bag];
    int e = off[bag + 1];
    float* o = out + (size_t)bag * 288;

    if (table == 0 || table == 3) {
        // dim 64: float2 per lane (256B/row), streamed.
        const float* W   = (table == 0) ? W0 : W3;
        const int*   ids = (table == 0) ? ids0 : ids3;
        int cb = (table == 0) ? 0 : 224;
        float2 acc0 = make_float2(0.f, 0.f);
        float2 acc1 = make_float2(0.f, 0.f);
        int j = s;
        for (; j + 8 <= e; j += 8) {
            const float2* p0 = (const float2*)(W + (size_t)ids[j + 0] * 64) + lane;
            const float2* p1 = (const float2*)(W + (size_t)ids[j + 1] * 64) + lane;
            const float2* p2 = (const float2*)(W + (size_t)ids[j + 2] * 64) + lane;
            const float2* p3 = (const float2*)(W + (size_t)ids[j + 3] * 64) + lane;
            const float2* p4 = (const float2*)(W + (size_t)ids[j + 4] * 64) + lane;
            const float2* p5 = (const float2*)(W + (size_t)ids[j + 5] * 64) + lane;
            const float2* p6 = (const float2*)(W + (size_t)ids[j + 6] * 64) + lane;
            const float2* p7 = (const float2*)(W + (size_t)ids[j + 7] * 64) + lane;
            float2 v0 = __ldcs(p0); float2 v1 = __ldcs(p1);
            float2 v2 = __ldcs(p2); float2 v3 = __ldcs(p3);
            float2 v4 = __ldcs(p4); float2 v5 = __ldcs(p5);
            float2 v6 = __ldcs(p6); float2 v7 = __ldcs(p7);
            acc0.x += v0.x + v1.x; acc0.y += v0.y + v1.y;
            acc1.x += v2.x + v3.x; acc1.y += v2.y + v3.y;
            acc0.x += v4.x + v5.x; acc0.y += v4.y + v5.y;
            acc1.x += v6.x + v7.x; acc1.y += v6.y + v7.y;
        }
        for (; j < e; j++) {
            float2 a = __ldcs((const float2*)(W + (size_t)ids[j] * 64) + lane);
            acc0.x += a.x; acc0.y += a.y;
        }
        acc0.x += acc1.x; acc0.y += acc1.y;
        __stcs((float2*)(o + cb) + lane, acc0);
    } else if (table == 1) {
        // dim 128: float4 per lane (512B/row). W1 = 51MB, keep L2-resident.
        float4 acc0 = make_float4(0.f, 0.f, 0.f, 0.f);
        float4 acc1 = make_float4(0.f, 0.f, 0.f, 0.f);
        int j = s;
        for (; j + 8 <= e; j += 8) {
            const float4* p0 = (const float4*)(W1 + (size_t)ids1[j + 0] * 128) + lane;
            const float4* p1 = (const float4*)(W1 + (size_t)ids1[j + 1] * 128) + lane;
            const float4* p2 = (const float4*)(W1 + (size_t)ids1[j + 2] * 128) + lane;
            const float4* p3 = (const float4*)(W1 + (size_t)ids1[j + 3] * 128) + lane;
            const float4* p4 = (const float4*)(W1 + (size_t)ids1[j + 4] * 128) + lane;
            const float4* p5 = (const float4*)(W1 + (size_t)ids1[j + 5] * 128) + lane;
            const float4* p6 = (const float4*)(W1 + (size_t)ids1[j + 6] * 128) + lane;
            const float4* p7 = (const float4*)(W1 + (size_t)ids1[j + 7] * 128) + lane;
            float4 v0 = *p0; float4 v1 = *p1; float4 v2 = *p2; float4 v3 = *p3;
            float4 v4 = *p4; float4 v5 = *p5; float4 v6 = *p6; float4 v7 = *p7;
            acc0.x += v0.x + v1.x; acc0.y += v0.y + v1.y;
            acc0.z += v0.z + v1.z; acc0.w += v0.w + v1.w;
            acc1.x += v2.x + v3.x; acc1.y += v2.y + v3.y;
            acc1.z += v2.z + v3.z; acc1.w += v2.w + v3.w;
            acc0.x += v4.x + v5.x; acc0.y += v4.y + v5.y;
            acc0.z += v4.z + v5.z; acc0.w += v4.w + v5.w;
            acc1.x += v6.x + v7.x; acc1.y += v6.y + v7.y;
            acc1.z += v6.z + v7.z; acc1.w += v6.w + v7.w;
        }
        for (; j < e; j++) {
            float4 a = *((const float4*)(W1 + (size_t)ids1[j] * 128) + lane);
            acc0.x += a.x; acc0.y += a.y; acc0.z += a.z; acc0.w += a.w;
        }
        acc0.x += acc1.x; acc0.y += acc1.y; acc0.z += acc1.z; acc0.w += acc1.w;
        __stcs((float4*)(o + 64) + lane, acc0);
    } else {
        // dim 32: 1 float per lane (128B/row). Unroll 16 (1 reg per load).
        float acc = 0.f;
        int j = s;
        for (; j + 16 <= e; j += 16) {
            float v[16];
#pragma unroll
            for (int k = 0; k < 16; k++)
                v[k] = W2[(size_t)ids2[j + k] * 32 + lane];
            float t0 = 0.f, t1 = 0.f, t2 = 0.f, t3 = 0.f;
#pragma unroll
            for (int k = 0; k < 16; k += 4) {
                t0 += v[k + 0]; t1 += v[k + 1]; t2 += v[k + 2]; t3 += v[k + 3];
            }
            acc += (t0 + t1) + (t2 + t3);
        }
        for (; j < e; j++) acc += W2[(size_t)ids2[j] * 32 + lane];
        __stcs(o + 192 + lane, acc);
    }
}

// ---------------------------------------------------------------------------
// kernel_launch: identify inputs by element count (order-robust), then launch.
// ---------------------------------------------------------------------------
extern "C" void kernel_launch(void* const* d_in, const int* in_sizes, int n_in,
                              void* d_out, int out_size) {
    const float *W0 = nullptr, *W1 = nullptr, *W2 = nullptr, *W3 = nullptr;
    const int *ids0 = nullptr, *ids1 = nullptr, *ids2 = nullptr, *ids3 = nullptr;
    const int *lens[4] = {nullptr, nullptr, nullptr, nullptr};
    int nlens = 0;
    bool seenW64 = false, seenIds819 = false;

    for (int i = 0; i < n_in; i++) {
        long long sz = in_sizes[i];
        void* p = d_in[i];
        if (sz == 64000000LL) {               // 1M x 64 (tables 0 and 3)
            if (!seenW64) { W0 = (const float*)p; seenW64 = true; }
            else          { W3 = (const float*)p; }
        } else if (sz == 12800000LL) {        // 100K x 128
            W1 = (const float*)p;
        } else if (sz == 16000000LL) {        // 500K x 32
            W2 = (const float*)p;
        } else if (sz == 819200LL) {          // ids for tables 0 and 3
            if (!seenIds819) { ids0 = (const int*)p; seenIds819 = true; }
            else             { ids3 = (const int*)p; }
        } else if (sz == 327680LL) {
            ids1 = (const int*)p;
        } else if (sz == 1638400LL) {
            ids2 = (const int*)p;
        } else if (sz == 16384LL) {
            if (nlens < 4) lens[nlens++] = (const int*)p;
        }
    }

    scan_kernel<<<4, 1024>>>(lens[0], lens[1], lens[2], lens[3]);
    pool_kernel<<<B_BAGS / 2, 256>>>(W0, W1, W2, W3,
                                     ids0, ids1, ids2, ids3,
                                     (float*)d_out);
}

// round 10
// speedup vs baseline: 1.0900x; 1.0900x over previous
#include <cuda_runtime.h>
#include <cstdint>

#define B_BAGS 16384

// Per-table exclusive prefix offsets (scratch, computed each launch).
__device__ int g_off[4][B_BAGS + 1];

// ---------------------------------------------------------------------------
// Scan kernel: one block per table, 1024 threads, 16 lens each, shfl-scan.
// ---------------------------------------------------------------------------
__global__ void scan_kernel(const int* __restrict__ l0, const int* __restrict__ l1,
                            const int* __restrict__ l2, const int* __restrict__ l3) {
    const int* lens = (blockIdx.x == 0) ? l0 : (blockIdx.x == 1) ? l1
                    : (blockIdx.x == 2) ? l2 : l3;
    int* off = g_off[blockIdx.x];
    __shared__ int warp_sums[32];

    int t    = threadIdx.x;
    int wid  = t >> 5;
    int lane = t & 31;

    int4 v0 = ((const int4*)lens)[t * 4 + 0];
    int4 v1 = ((const int4*)lens)[t * 4 + 1];
    int4 v2 = ((const int4*)lens)[t * 4 + 2];
    int4 v3 = ((const int4*)lens)[t * 4 + 3];
    int vals[16] = {v0.x, v0.y, v0.z, v0.w, v1.x, v1.y, v1.z, v1.w,
                    v2.x, v2.y, v2.z, v2.w, v3.x, v3.y, v3.z, v3.w};

    int s = 0;
    int pre[16];
#pragma unroll
    for (int k = 0; k < 16; k++) { pre[k] = s; s += vals[k]; }

    int incl = s;
#pragma unroll
    for (int d = 1; d < 32; d <<= 1) {
        int x = __shfl_up_sync(0xffffffffu, incl, d);
        if (lane >= d) incl += x;
    }
    if (lane == 31) warp_sums[wid] = incl;
    __syncthreads();

    if (wid == 0) {
        int w = warp_sums[lane];
        int wincl = w;
#pragma unroll
        for (int d = 1; d < 32; d <<= 1) {
            int x = __shfl_up_sync(0xffffffffu, wincl, d);
            if (lane >= d) wincl += x;
        }
        warp_sums[lane] = wincl - w;
    }
    __syncthreads();

    int base = warp_sums[wid] + (incl - s);
#pragma unroll
    for (int k = 0; k < 16; k++) off[t * 16 + k] = base + pre[k];
    if (t == 1023) off[B_BAGS] = base + s;
}

// ---------------------------------------------------------------------------
// Pooling kernel: warp per (bag, table), 8 warps/block.
// Grid is table-INTERLEAVED: table = blockIdx.x & 3, so every resident wave
// mixes DRAM-heavy tables (0/3, 256MB each) with L2-resident tables (1/2),
// overlapping DRAM and L2 service instead of running them in phases.
// Loop bodies identical to the best (R7) version: regs=32, occ ~84%.
// Output layout: [B, 288], column bases {0, 64, 192, 224}.
// ---------------------------------------------------------------------------
__global__ __launch_bounds__(256)
void pool_kernel(const float* __restrict__ W0, const float* __restrict__ W1,
                 const float* __restrict__ W2, const float* __restrict__ W3,
                 const int* __restrict__ ids0, const int* __restrict__ ids1,
                 const int* __restrict__ ids2, const int* __restrict__ ids3,
                 float* __restrict__ out) {
    int table = blockIdx.x & 3;                               // interleaved
    int bag   = ((blockIdx.x >> 2) << 3) + (threadIdx.x >> 5);
    int lane  = threadIdx.x & 31;

    const int* off = g_off[table];
    int s = off[bag];
    int e = off[bag + 1];
    float* o = out + (size_t)bag * 288;

    if (table == 0 || table == 3) {
        // dim 64: float2 per lane (256B/row). Streamed (.cs) — tables are 256MB.
        const float* W   = (table == 0) ? W0 : W3;
        const int*   ids = (table == 0) ? ids0 : ids3;
        int cb = (table == 0) ? 0 : 224;
        float2 acc = make_float2(0.f, 0.f);
        int j = s;
        for (; j + 8 <= e; j += 8) {
            int idx[8];
#pragma unroll
            for (int k = 0; k < 8; k++) idx[k] = ids[j + k];
            float2 v[8];
#pragma unroll
            for (int k = 0; k < 8; k++)
                v[k] = __ldcs((const float2*)(W + (size_t)idx[k] * 64) + lane);
#pragma unroll
            for (int k = 0; k < 8; k++) { acc.x += v[k].x; acc.y += v[k].y; }
        }
        for (; j < e; j++) {
            float2 a = __ldcs((const float2*)(W + (size_t)ids[j] * 64) + lane);
            acc.x += a.x; acc.y += a.y;
        }
        __stcs((float2*)(o + cb) + lane, acc);
    } else if (table == 1) {
        // dim 128: float4 per lane (512B/row). W1 = 51MB, want L2-resident.
        float4 acc = make_float4(0.f, 0.f, 0.f, 0.f);
        int j = s;
        for (; j + 8 <= e; j += 8) {
            int idx[8];
#pragma unroll
            for (int k = 0; k < 8; k++) idx[k] = ids1[j + k];
            float4 v[8];
#pragma unroll
            for (int k = 0; k < 8; k++)
                v[k] = *((const float4*)(W1 + (size_t)idx[k] * 128) + lane);
#pragma unroll
            for (int k = 0; k < 8; k++) {
                acc.x += v[k].x; acc.y += v[k].y; acc.z += v[k].z; acc.w += v[k].w;
            }
        }
        for (; j < e; j++) {
            float4 a = *((const float4*)(W1 + (size_t)ids1[j] * 128) + lane);
            acc.x += a.x; acc.y += a.y; acc.z += a.z; acc.w += a.w;
        }
        __stcs((float4*)(o + 64) + lane, acc);
    } else {
        // dim 32: 1 float per lane (128B/row). W2 = 64MB, want L2-resident.
        float acc = 0.f;
        int j = s;
        for (; j + 8 <= e; j += 8) {
            int idx[8];
#pragma unroll
            for (int k = 0; k < 8; k++) idx[k] = ids2[j + k];
            float v[8];
#pragma unroll
            for (int k = 0; k < 8; k++) v[k] = W2[(size_t)idx[k] * 32 + lane];
#pragma unroll
            for (int k = 0; k < 8; k++) acc += v[k];
        }
        for (; j < e; j++) acc += W2[(size_t)ids2[j] * 32 + lane];
        __stcs(o + 192 + lane, acc);
    }
}

// ---------------------------------------------------------------------------
// kernel_launch: identify inputs by element count (order-robust), then launch.
// ---------------------------------------------------------------------------
extern "C" void kernel_launch(void* const* d_in, const int* in_sizes, int n_in,
                              void* d_out, int out_size) {
    const float *W0 = nullptr, *W1 = nullptr, *W2 = nullptr, *W3 = nullptr;
    const int *ids0 = nullptr, *ids1 = nullptr, *ids2 = nullptr, *ids3 = nullptr;
    const int *lens[4] = {nullptr, nullptr, nullptr, nullptr};
    int nlens = 0;
    bool seenW64 = false, seenIds819 = false;

    for (int i = 0; i < n_in; i++) {
        long long sz = in_sizes[i];
        void* p = d_in[i];
        if (sz == 64000000LL) {               // 1M x 64 (tables 0 and 3)
            if (!seenW64) { W0 = (const float*)p; seenW64 = true; }
            else          { W3 = (const float*)p; }
        } else if (sz == 12800000LL) {        // 100K x 128
            W1 = (const float*)p;
        } else if (sz == 16000000LL) {        // 500K x 32
            W2 = (const float*)p;
        } else if (sz == 819200LL) {          // ids for tables 0 and 3
            if (!seenIds819) { ids0 = (const int*)p; seenIds819 = true; }
            else             { ids3 = (const int*)p; }
        } else if (sz == 327680LL) {
            ids1 = (const int*)p;
        } else if (sz == 1638400LL) {
            ids2 = (const int*)p;
        } else if (sz == 16384LL) {
            if (nlens < 4) lens[nlens++] = (const int*)p;
        }
    }

    scan_kernel<<<4, 1024>>>(lens[0], lens[1], lens[2], lens[3]);
    pool_kernel<<<B_BAGS / 2, 256>>>(W0, W1, W2, W3,
                                     ids0, ids1, ids2, ids3,
                                     (float*)d_out);
}